// round 8
// baseline (speedup 1.0000x reference)
#include <cuda_runtime.h>
#include <cuda_bf16.h>

#define Cc    9
#define OUTc  16
#define NBc   16
#define Vc    20000
#define Bc    2

// padded x: 3 float4 per row (48 B)
__device__ __align__(16) float4 xpad[Bc * Vc * 3];

__global__ __launch_bounds__(256)
void pad_kernel(const float* __restrict__ x)
{
    int r = blockIdx.x * blockDim.x + threadIdx.x;   // row over B*V
    if (r >= Bc * Vc) return;
    const float* src = x + (size_t)r * Cc;
    float4* dst = xpad + (size_t)r * 3;
    dst[0] = make_float4(__ldg(&src[0]), __ldg(&src[1]), __ldg(&src[2]), __ldg(&src[3]));
    dst[1] = make_float4(__ldg(&src[4]), __ldg(&src[5]), __ldg(&src[6]), __ldg(&src[7]));
    dst[2] = make_float4(__ldg(&src[8]), 0.0f, 0.0f, 0.0f);
}

__global__ __launch_bounds__(128, 5)
void nlayer_kernel(const float* __restrict__ W,
                   const int*   __restrict__ adj,
                   float*       __restrict__ out)
{
    // +16 pad (zeroed) absorbs the dead-slot clamped read at c=8
    __shared__ float Wsh[Cc * Cc * OUTc + 16];
    for (int i = threadIdx.x; i < Cc * Cc * OUTc + 16; i += blockDim.x)
        Wsh[i] = (i < Cc * Cc * OUTc) ? W[i] : 0.0f;
    __syncthreads();

    int tid   = blockIdx.x * blockDim.x + threadIdx.x;  // 640000 total, exact
    int group = tid >> 4;          // vertex over B*V
    int l     = tid & 15;
    int p     = l & 3;             // k-quarter: {0,1,2},{3,4},{5,6},{7,8}
    int q     = l >> 2;            // neighbor quarter AND o-quarter

    int b = (group >= Vc) ? 1 : 0;
    int v = group - b * Vc;
    const float4* tb = xpad + (size_t)(b * Vc) * 3;

    // ---- load burst (independent, front-issued) ----
    float4 c0 = __ldg(&tb[(size_t)v * 3 + 0]);   // merged across 16 lanes
    float4 c1 = __ldg(&tb[(size_t)v * 3 + 1]);
    float4 c2 = __ldg(&tb[(size_t)v * 3 + 2]);

    int4 av = __ldg(reinterpret_cast<const int4*>(adj + (size_t)v * NBc) + q);
    int a[4] = {av.x, av.y, av.z, av.w};

    float4 r0[4], r1[4], r2[4];
    int valid[4];
    int deg = 0;
    #pragma unroll
    for (int n = 0; n < 4; n++) {
        valid[n] = (a[n] != 0);
        deg += valid[n];
        int ridx = valid[n] ? (a[n] - 1) : 0;
        const float4* nr = tb + (size_t)ridx * 3;
        r0[n] = __ldg(&nr[0]);
        r1[n] = __ldg(&nr[1]);
        r2[n] = __ldg(&nr[2]);
    }

    // center features at this lane's k-slots (k0 = 0/3/5/7)
    float xc0 = (p == 0) ? c0.x : (p == 1) ? c0.w : (p == 2) ? c1.y : c1.w;
    float xc1 = (p == 0) ? c0.y : (p == 1) ? c1.x : (p == 2) ? c1.z : c2.x;
    float xc2 = c0.z;                          // only meaningful for p==0

    float s0[Cc], s1[Cc], s2[Cc];
    #pragma unroll
    for (int c = 0; c < Cc; c++) { s0[c] = 0.0f; s1[c] = 0.0f; s2[c] = 0.0f; }

    #pragma unroll
    for (int n = 0; n < 4; n++) {
        float4 n0 = r0[n], n1 = r1[n], n2 = r2[n];

        float nb0 = (p == 0) ? n0.x : (p == 1) ? n0.w : (p == 2) ? n1.y : n1.w;
        float nb1 = (p == 0) ? n0.y : (p == 1) ? n1.x : (p == 2) ? n1.z : n2.x;

        float e0 = __expf(xc0 - nb0);
        float e1 = __expf(xc1 - nb1);
        float e2 = (p == 0) ? __expf(xc2 - n0.z) : 0.0f;  // dead slot -> exactly 0

        // softmax denominator: combine the 4 k-quarters (p-lanes)
        float part = e0 + e1 + e2;
        part += __shfl_xor_sync(0xffffffffu, part, 1);
        part += __shfl_xor_sync(0xffffffffu, part, 2);
        float rr = valid[n] ? __fdividef(1.0f, part) : 0.0f;

        float g0 = e0 * rr, g1 = e1 * rr, g2 = e2 * rr;

        float nbv[Cc] = {n0.x, n0.y, n0.z, n0.w, n1.x, n1.y, n1.z, n1.w, n2.x};
        #pragma unroll
        for (int c = 0; c < Cc; c++) {
            s0[c] = fmaf(g0, nbv[c], s0[c]);
            s1[c] = fmaf(g1, nbv[c], s1[c]);
            s2[c] = fmaf(g2, nbv[c], s2[c]);
        }
    }

    // reduce s and deg across the 4 neighbor quarters (q bits: xor4, xor8)
    deg += __shfl_xor_sync(0xffffffffu, deg, 4);
    deg += __shfl_xor_sync(0xffffffffu, deg, 8);
    #pragma unroll
    for (int c = 0; c < Cc; c++) {
        float t0 = s0[c], t1 = s1[c], t2 = s2[c];
        t0 += __shfl_xor_sync(0xffffffffu, t0, 4);
        t1 += __shfl_xor_sync(0xffffffffu, t1, 4);
        t2 += __shfl_xor_sync(0xffffffffu, t2, 4);
        t0 += __shfl_xor_sync(0xffffffffu, t0, 8);
        t1 += __shfl_xor_sync(0xffffffffu, t1, 8);
        t2 += __shfl_xor_sync(0xffffffffu, t2, 8);
        s0[c] = t0; s1[c] = t1; s2[c] = t2;
    }

    float invdeg = (deg > 0) ? (1.0f / (float)deg) : 0.0f;

    // contraction: lane's k-quarter into o-quarter [4q, 4q+4)
    int k0 = (p == 0) ? 0 : (p == 1) ? 3 : (p == 2) ? 5 : 7;
    const float* wb = Wsh + k0 * OUTc + 4 * q;

    float a0 = 0.0f, a1 = 0.0f, a2 = 0.0f, a3 = 0.0f;
    #pragma unroll
    for (int c = 0; c < Cc; c++) {
        float sc0 = s0[c], sc1 = s1[c], sc2 = s2[c];
        const float* wc = wb + c * (Cc * OUTc);
        float4 w0 = *reinterpret_cast<const float4*>(wc);
        float4 w1 = *reinterpret_cast<const float4*>(wc + OUTc);
        float4 w2 = *reinterpret_cast<const float4*>(wc + 2 * OUTc); // dead for p>0: sc2==0
        a0 = fmaf(sc0, w0.x, a0); a1 = fmaf(sc0, w0.y, a1);
        a2 = fmaf(sc0, w0.z, a2); a3 = fmaf(sc0, w0.w, a3);
        a0 = fmaf(sc1, w1.x, a0); a1 = fmaf(sc1, w1.y, a1);
        a2 = fmaf(sc1, w1.z, a2); a3 = fmaf(sc1, w1.w, a3);
        a0 = fmaf(sc2, w2.x, a0); a1 = fmaf(sc2, w2.y, a1);
        a2 = fmaf(sc2, w2.z, a2); a3 = fmaf(sc2, w2.w, a3);
    }

    // combine the 4 k-quarters (p bits: xor1, xor2)
    a0 += __shfl_xor_sync(0xffffffffu, a0, 1);
    a1 += __shfl_xor_sync(0xffffffffu, a1, 1);
    a2 += __shfl_xor_sync(0xffffffffu, a2, 1);
    a3 += __shfl_xor_sync(0xffffffffu, a3, 1);
    a0 += __shfl_xor_sync(0xffffffffu, a0, 2);
    a1 += __shfl_xor_sync(0xffffffffu, a1, 2);
    a2 += __shfl_xor_sync(0xffffffffu, a2, 2);
    a3 += __shfl_xor_sync(0xffffffffu, a3, 2);

    // lane l stores out[group*16 + l]  (o = 4q + p -> acc[p]); 128B/warp coalesced
    float r = (p == 0) ? a0 : (p == 1) ? a1 : (p == 2) ? a2 : a3;
    out[(size_t)group * OUTc + l] = fmaxf(r * invdeg, 0.0f);
}

extern "C" void kernel_launch(void* const* d_in, const int* in_sizes, int n_in,
                              void* d_out, int out_size)
{
    const float* x   = (const float*)d_in[0];   // (2, 20000, 9)
    const float* W   = (const float*)d_in[1];   // (9, 9, 16)
    const int*   adj = (const int*)d_in[2];     // (20000, 16)
    float*       out = (float*)d_out;           // (2, 20000, 16)

    {
        const int total   = Bc * Vc;            // 40000
        const int threads = 256;
        pad_kernel<<<(total + threads - 1) / threads, threads>>>(x);
    }
    {
        const int total   = Bc * Vc * 16;       // 640000
        const int threads = 128;
        nlayer_kernel<<<total / threads, threads>>>(W, adj, out);
    }
}

// round 9
// speedup vs baseline: 2.2549x; 2.2549x over previous
#include <cuda_runtime.h>
#include <cuda_bf16.h>

#define Cc    9
#define OUTc  16
#define NBc   16
#define Vc    20000
#define Bc    2

// padded x: 3 float4 per row (48 B)
__device__ __align__(16) float4 xpad[Bc * Vc * 3];

__global__ __launch_bounds__(256)
void pad_kernel(const float* __restrict__ x)
{
    int r = blockIdx.x * blockDim.x + threadIdx.x;   // row over B*V
    if (r >= Bc * Vc) return;
    const float* src = x + (size_t)r * Cc;
    float4* dst = xpad + (size_t)r * 3;
    dst[0] = make_float4(__ldg(&src[0]), __ldg(&src[1]), __ldg(&src[2]), __ldg(&src[3]));
    dst[1] = make_float4(__ldg(&src[4]), __ldg(&src[5]), __ldg(&src[6]), __ldg(&src[7]));
    dst[2] = make_float4(__ldg(&src[8]), 0.0f, 0.0f, 0.0f);
}

__global__ __launch_bounds__(128, 3)
void nlayer_kernel(const float* __restrict__ W,
                   const int*   __restrict__ adj,
                   float*       __restrict__ out)
{
    __shared__ float Wsh[Cc * Cc * OUTc];    // W[c][k][o], 1296 floats
    for (int i = threadIdx.x; i < Cc * Cc * OUTc; i += blockDim.x)
        Wsh[i] = W[i];
    __syncthreads();

    int tid   = blockIdx.x * blockDim.x + threadIdx.x;   // 80000 total, exact
    int group = tid >> 1;          // vertex over B*V
    int p     = tid & 1;           // neighbor half AND output half

    int b = (group >= Vc) ? 1 : 0;
    int v = group - b * Vc;
    const float4* tb = xpad + (size_t)(b * Vc) * 3;

    // center row (both lanes same address -> merged)
    float4 c0 = __ldg(&tb[(size_t)v * 3 + 0]);
    float4 c1 = __ldg(&tb[(size_t)v * 3 + 1]);
    float4 c2 = __ldg(&tb[(size_t)v * 3 + 2]);
    float xv[Cc] = {c0.x, c0.y, c0.z, c0.w, c1.x, c1.y, c1.z, c1.w, c2.x};

    // this lane's 8 neighbors (no duplication: each row loaded once chip-wide)
    const int4* adj4 = reinterpret_cast<const int4*>(adj + (size_t)v * NBc);
    int4 a0 = __ldg(&adj4[2 * p + 0]);
    int4 a1 = __ldg(&adj4[2 * p + 1]);
    int av[8] = {a0.x, a0.y, a0.z, a0.w, a1.x, a1.y, a1.z, a1.w};

    float s[Cc][Cc];   // s[k][c], partial over this lane's neighbors
    #pragma unroll
    for (int k = 0; k < Cc; k++)
        #pragma unroll
        for (int c = 0; c < Cc; c++) s[k][c] = 0.0f;

    int deg = 0;

    // two bursts of 4 rows: loads front-issued (MLP=12), then processed
    #pragma unroll
    for (int g = 0; g < 2; g++) {
        float4 R0[4], R1[4], R2[4];
        int vld[4];
        #pragma unroll
        for (int n = 0; n < 4; n++) {
            int an = av[g * 4 + n];
            vld[n] = (an != 0);
            deg   += vld[n];
            int ridx = vld[n] ? (an - 1) : 0;
            const float4* nr = tb + (size_t)ridx * 3;
            R0[n] = __ldg(&nr[0]);
            R1[n] = __ldg(&nr[1]);
            R2[n] = __ldg(&nr[2]);
        }

        #pragma unroll
        for (int n = 0; n < 4; n++) {
            float nbv[Cc] = {R0[n].x, R0[n].y, R0[n].z, R0[n].w,
                             R1[n].x, R1[n].y, R1[n].z, R1[n].w, R2[n].x};
            float e[Cc], sum = 0.0f;
            #pragma unroll
            for (int c = 0; c < Cc; c++) {
                e[c] = __expf(xv[c] - nbv[c]);
                sum += e[c];
            }
            float rr = vld[n] ? __fdividef(1.0f, sum) : 0.0f;

            #pragma unroll
            for (int k = 0; k < Cc; k++) {
                float qk = e[k] * rr;
                #pragma unroll
                for (int c = 0; c < Cc; c++)
                    s[k][c] = fmaf(qk, nbv[c], s[k][c]);
            }
        }
    }

    // single reduction round across the lane pair; both lanes get FULL s
    deg += __shfl_xor_sync(0xffffffffu, deg, 1);
    #pragma unroll
    for (int k = 0; k < Cc; k++)
        #pragma unroll
        for (int c = 0; c < Cc; c++)
            s[k][c] += __shfl_xor_sync(0xffffffffu, s[k][c], 1);

    float invdeg = (deg > 0) ? (1.0f / (float)deg) : 0.0f;

    // lane p contracts full s into its o-half [8p, 8p+8); no post-reduction
    float acc[8];
    #pragma unroll
    for (int o = 0; o < 8; o++) acc[o] = 0.0f;

    const float* wb = Wsh + 8 * p;
    #pragma unroll
    for (int c = 0; c < Cc; c++) {
        #pragma unroll
        for (int k = 0; k < Cc; k++) {
            float sc = s[k][c];
            const float* wr = wb + (c * Cc + k) * OUTc;
            float4 w0 = *reinterpret_cast<const float4*>(wr);
            float4 w1 = *reinterpret_cast<const float4*>(wr + 4);
            acc[0] = fmaf(sc, w0.x, acc[0]);
            acc[1] = fmaf(sc, w0.y, acc[1]);
            acc[2] = fmaf(sc, w0.z, acc[2]);
            acc[3] = fmaf(sc, w0.w, acc[3]);
            acc[4] = fmaf(sc, w1.x, acc[4]);
            acc[5] = fmaf(sc, w1.y, acc[5]);
            acc[6] = fmaf(sc, w1.z, acc[6]);
            acc[7] = fmaf(sc, w1.w, acc[7]);
        }
    }

    // lane p stores outputs [8p, 8p+8): two float4, coalesced
    float* op = out + (size_t)group * OUTc + 8 * p;
    float4 o0, o1;
    o0.x = fmaxf(acc[0] * invdeg, 0.0f);
    o0.y = fmaxf(acc[1] * invdeg, 0.0f);
    o0.z = fmaxf(acc[2] * invdeg, 0.0f);
    o0.w = fmaxf(acc[3] * invdeg, 0.0f);
    o1.x = fmaxf(acc[4] * invdeg, 0.0f);
    o1.y = fmaxf(acc[5] * invdeg, 0.0f);
    o1.z = fmaxf(acc[6] * invdeg, 0.0f);
    o1.w = fmaxf(acc[7] * invdeg, 0.0f);
    *reinterpret_cast<float4*>(op)     = o0;
    *reinterpret_cast<float4*>(op + 4) = o1;
}

extern "C" void kernel_launch(void* const* d_in, const int* in_sizes, int n_in,
                              void* d_out, int out_size)
{
    const float* x   = (const float*)d_in[0];   // (2, 20000, 9)
    const float* W   = (const float*)d_in[1];   // (9, 9, 16)
    const int*   adj = (const int*)d_in[2];     // (20000, 16)
    float*       out = (float*)d_out;           // (2, 20000, 16)

    {
        const int total   = Bc * Vc;            // 40000
        const int threads = 256;
        pad_kernel<<<(total + threads - 1) / threads, threads>>>(x);
    }
    {
        const int total   = Bc * Vc * 2;        // 80000
        const int threads = 128;
        nlayer_kernel<<<total / threads, threads>>>(W, adj, out);
    }
}